// round 13
// baseline (speedup 1.0000x reference)
#include <cuda_runtime.h>
#include <math.h>
#include <stdint.h>

// ---------------------------------------------------------------------------
// Problem constants
// ---------------------------------------------------------------------------
#define DIMD  1024
#define BATCH 8
#define SEQ   4096
#define MTOT  (BATCH * SEQ)
#define NSCAN 128
#define EPER  (DIMD / NSCAN)   // 8

// ---------------------------------------------------------------------------
// Scratch (device-global; no allocation allowed)
// ---------------------------------------------------------------------------
__device__ float    g_inp [(size_t)MTOT * DIMD];
__device__ float    g_gate[(size_t)MTOT * DIMD];
__device__ float    g_u   [(size_t)MTOT * DIMD];
// pre-split bf16 operands (hi = truncation, lo = rn(residual))
__device__ unsigned short g_xh[(size_t)MTOT * DIMD];
__device__ unsigned short g_xl[(size_t)MTOT * DIMD];
__device__ unsigned short g_ih[(size_t)MTOT * DIMD];
__device__ unsigned short g_il[(size_t)MTOT * DIMD];
__device__ unsigned short g_sh[(size_t)MTOT * DIMD];
__device__ unsigned short g_sl[(size_t)MTOT * DIMD];
__device__ unsigned short g_wh[4][DIMD * DIMD];
__device__ unsigned short g_wl[4][DIMD * DIMD];
__device__ uint32_t g_sp[2][BATCH * DIMD];   // packed scan state (bf16hi | bf16lo<<16)
__device__ unsigned g_counter;

// ---------------------------------------------------------------------------
// Helpers
// ---------------------------------------------------------------------------
__device__ __forceinline__ uint32_t smem_u32(const void* p) {
    uint32_t a;
    asm("{ .reg .u64 t; cvta.to.shared.u64 t, %1; cvt.u32.u64 %0, t; }" : "=r"(a) : "l"(p));
    return a;
}

#define LDSM4(r, addr)                                                        \
    asm volatile("ldmatrix.sync.aligned.m8n8.x4.shared.b16 {%0,%1,%2,%3}, [%4];" \
        : "=r"((r)[0]), "=r"((r)[1]), "=r"((r)[2]), "=r"((r)[3]) : "r"(addr))

#define MMA16816(d, a, b)                                                     \
    asm volatile("mma.sync.aligned.m16n8k16.row.col.f32.bf16.bf16.f32 "       \
        "{%0,%1,%2,%3}, {%4,%5,%6,%7}, {%8,%9}, {%0,%1,%2,%3};"               \
        : "+f"((d)[0]), "+f"((d)[1]), "+f"((d)[2]), "+f"((d)[3])              \
        : "r"((a)[0]), "r"((a)[1]), "r"((a)[2]), "r"((a)[3]),                 \
          "r"((b)[0]), "r"((b)[1]))

#define CP_ASYNC16(smem_addr, gptr)                                           \
    asm volatile("cp.async.cg.shared.global [%0], [%1], 16;"                  \
        :: "r"(smem_addr), "l"(gptr) : "memory")
#define CP_COMMIT() asm volatile("cp.async.commit_group;" ::: "memory")
#define CP_WAIT(n)  asm volatile("cp.async.wait_group %0;" :: "n"(n) : "memory")

__device__ __forceinline__ uint32_t hipack(float x0, float x1) {
    return __byte_perm(__float_as_uint(x0), __float_as_uint(x1), 0x7632);
}
__device__ __forceinline__ uint32_t lopack(float x0, float x1) {
    float t0 = __uint_as_float(__float_as_uint(x0) & 0xFFFF0000u);
    float t1 = __uint_as_float(__float_as_uint(x1) & 0xFFFF0000u);
    float r0 = x0 - t0, r1 = x1 - t1;
    uint32_t d;
    asm("cvt.rn.bf16x2.f32 %0, %1, %2;" : "=r"(d) : "f"(r1), "f"(r0));
    return d;
}

__device__ __forceinline__ uint4 ldcg4(const uint4* p) {
    uint4 v;
    asm volatile("ld.global.cg.v4.u32 {%0,%1,%2,%3}, [%4];"
                 : "=r"(v.x), "=r"(v.y), "=r"(v.z), "=r"(v.w) : "l"(p));
    return v;
}
__device__ __forceinline__ void red_release_add1(unsigned* p) {
    asm volatile("red.release.gpu.global.add.u32 [%0], 1;" :: "l"(p) : "memory");
}
__device__ __forceinline__ unsigned ld_acquire(const unsigned* p) {
    unsigned v;
    asm volatile("ld.acquire.gpu.global.u32 %0, [%1];" : "=r"(v) : "l"(p) : "memory");
    return v;
}

// ---------------------------------------------------------------------------
// Init kernel
// ---------------------------------------------------------------------------
__global__ void init_kernel() {
    int t = blockIdx.x * blockDim.x + threadIdx.x;
    if (t < BATCH * DIMD) { g_sp[0][t] = 0u; g_sp[1][t] = 0u; }
    if (t == 0) g_counter = 0u;
}

// ---------------------------------------------------------------------------
// Elementwise fp32 -> (hi, lo) bf16 split, 4 elems/thread
// ---------------------------------------------------------------------------
__global__ void split_kernel(const float4* __restrict__ X,
                             uint2* __restrict__ H, uint2* __restrict__ L, int n4)
{
    int i = blockIdx.x * blockDim.x + threadIdx.x;
    if (i < n4) {
        float4 v = X[i];
        uint2 h, l;
        h.x = hipack(v.x, v.y); h.y = hipack(v.z, v.w);
        l.x = lopack(v.x, v.y); l.y = lopack(v.z, v.w);
        H[i] = h; L[i] = l;
    }
}

// ---------------------------------------------------------------------------
// cp.async bf16 3x-split tensor-core GEMM (NT).
// Pre-split operands. K-chunk 32 (2 sub-chunks of 16), double-buffered via
// LDGSTS (no register staging, no in-loop split ALU). 2 syncthreads / 32 k.
// SMEM stage: 4 tiles (Ahi, Alo, Bhi, Blo), each 128 rows x 64B, XOR-swizzled
// q' = q ^ ((row>>1)&3) -- conflict-free for both cp.async STS and ldmatrix.
// ---------------------------------------------------------------------------
#define GK 1024
#define GN 1024
#define NSTAGEK 32
#define NCH32 (GK / NSTAGEK)        // 32
#define TILEB 8192                  // 128 * 64B
#define STAGEB (4 * TILEB)          // 32KB
#define GEMM_SMEM (2 * STAGEB)      // 64KB dynamic

template <int EPI, int WSPLIT>
__global__ __launch_bounds__(256, 2)
void gemm_cp(const unsigned short* __restrict__ Xh, const unsigned short* __restrict__ Xl,
             const unsigned short* __restrict__ Wh, const unsigned short* __restrict__ Wl,
             const float* __restrict__ bias, float* __restrict__ C,
             unsigned short* __restrict__ Ch, unsigned short* __restrict__ Cl)
{
    extern __shared__ __align__(1024) unsigned char sm[];

    const int tid = threadIdx.x;
    const int wid = tid >> 5, l = tid & 31;
    const int bm = blockIdx.y * 128, bn = blockIdx.x * 128;
    const int wm = wid & 1, wn = wid >> 1;

    const uint32_t smbase = smem_u32(sm);

    // cp.async mapping: thread handles units u = 2*tid, 2*tid+1 of each tile
    // unit u: row = u>>2, q = u&3 ; dst = row*64 + 16*(q ^ ((row>>1)&3))
    const int u0 = 2 * tid;
    const int r0 = u0 >> 2, q0 = u0 & 3;
    const int r1 = (u0 + 1) >> 2, q1 = (u0 + 1) & 3;
    const uint32_t d0 = (uint32_t)(r0 * 64 + 16 * (q0 ^ ((r0 >> 1) & 3)));
    const uint32_t d1 = (uint32_t)(r1 * 64 + 16 * (q1 ^ ((r1 >> 1) & 3)));
    // gmem: element offset = row*GK + kc + q*8 (bf16)
    const unsigned short* gA0h = Xh + (size_t)(bm + r0) * GK + q0 * 8;
    const unsigned short* gA1h = Xh + (size_t)(bm + r1) * GK + q1 * 8;
    const unsigned short* gA0l = Xl + (size_t)(bm + r0) * GK + q0 * 8;
    const unsigned short* gA1l = Xl + (size_t)(bm + r1) * GK + q1 * 8;
    const unsigned short* gB0h = Wh + (size_t)(bn + r0) * GK + q0 * 8;
    const unsigned short* gB1h = Wh + (size_t)(bn + r1) * GK + q1 * 8;
    const unsigned short* gB0l = Wl + (size_t)(bn + r0) * GK + q0 * 8;
    const unsigned short* gB1l = Wl + (size_t)(bn + r1) * GK + q1 * 8;

    // ldmatrix lane geometry: lane row + k-half
    const int lrow = l & 15, lhalf = l >> 4;

    float acc[4][4][4];
#pragma unroll
    for (int mi = 0; mi < 4; mi++)
#pragma unroll
        for (int ni = 0; ni < 4; ni++)
#pragma unroll
            for (int r = 0; r < 4; r++) acc[mi][ni][r] = 0.f;

    // issue stage for chunk c into buffer (c&1)
    auto issue = [&](int c) {
        const int kc = c * NSTAGEK;
        const uint32_t st = smbase + (uint32_t)(c & 1) * STAGEB;
        CP_ASYNC16(st + 0 * TILEB + d0, gA0h + kc);
        CP_ASYNC16(st + 0 * TILEB + d1, gA1h + kc);
        CP_ASYNC16(st + 1 * TILEB + d0, gA0l + kc);
        CP_ASYNC16(st + 1 * TILEB + d1, gA1l + kc);
        CP_ASYNC16(st + 2 * TILEB + d0, gB0h + kc);
        CP_ASYNC16(st + 2 * TILEB + d1, gB1h + kc);
        CP_ASYNC16(st + 3 * TILEB + d0, gB0l + kc);
        CP_ASYNC16(st + 3 * TILEB + d1, gB1l + kc);
        CP_COMMIT();
    };

    issue(0);

    for (int c = 0; c < NCH32; c++) {
        if (c + 1 < NCH32) {
            issue(c + 1);
            CP_WAIT(1);
        } else {
            CP_WAIT(0);
        }
        __syncthreads();   // stage (c&1) data visible to all warps

        const uint32_t st = smbase + (uint32_t)(c & 1) * STAGEB;

#pragma unroll
        for (int c2 = 0; c2 < 2; c2++) {
            // A fragments: tile rows wm*64 + mi*16 + lrow, quadrant 2*c2+lhalf
            uint32_t ah[4][4], al[4][4];
#pragma unroll
            for (int mi = 0; mi < 4; mi++) {
                int row = wm * 64 + mi * 16 + lrow;
                uint32_t off = (uint32_t)(row * 64 + 16 * ((2 * c2 + lhalf) ^ ((row >> 1) & 3)));
                LDSM4(ah[mi], st + 0 * TILEB + off);
                LDSM4(al[mi], st + 1 * TILEB + off);
            }
            uint32_t bh[4][2], bl[4][2];
#pragma unroll
            for (int gi = 0; gi < 2; gi++) {
                int row = wn * 32 + gi * 16 + lrow;
                uint32_t off = (uint32_t)(row * 64 + 16 * ((2 * c2 + lhalf) ^ ((row >> 1) & 3)));
                uint32_t t[4];
                LDSM4(t, st + 2 * TILEB + off);
                bh[2 * gi + 0][0] = t[0]; bh[2 * gi + 0][1] = t[2];
                bh[2 * gi + 1][0] = t[1]; bh[2 * gi + 1][1] = t[3];
                LDSM4(t, st + 3 * TILEB + off);
                bl[2 * gi + 0][0] = t[0]; bl[2 * gi + 0][1] = t[2];
                bl[2 * gi + 1][0] = t[1]; bl[2 * gi + 1][1] = t[3];
            }

#pragma unroll
            for (int mi = 0; mi < 4; mi++)
#pragma unroll
                for (int ni = 0; ni < 4; ni++)
                    MMA16816(acc[mi][ni], ah[mi], bh[ni]);
#pragma unroll
            for (int mi = 0; mi < 4; mi++)
#pragma unroll
                for (int ni = 0; ni < 4; ni++)
                    MMA16816(acc[mi][ni], ah[mi], bl[ni]);
#pragma unroll
            for (int mi = 0; mi < 4; mi++)
#pragma unroll
                for (int ni = 0; ni < 4; ni++)
                    MMA16816(acc[mi][ni], al[mi], bh[ni]);
        }

        __syncthreads();   // all warps done with stage (c&1) before reuse
    }

    // --- epilogue
    const int erow  = bm + wm * 64 + (l >> 2);
    const int ecol0 = bn + wn * 32 + 2 * (l & 3);

    float2 bv[4];
#pragma unroll
    for (int ni = 0; ni < 4; ni++) {
        if (bias) {
            bv[ni].x = bias[ecol0 + ni * 8];
            bv[ni].y = bias[ecol0 + ni * 8 + 1];
        } else {
            bv[ni].x = 0.f; bv[ni].y = 0.f;
        }
    }

#pragma unroll
    for (int mi = 0; mi < 4; mi++) {
#pragma unroll
        for (int ni = 0; ni < 4; ni++) {
            const int r = erow + mi * 16;
            float2 v0, v1;
            v0.x = acc[mi][ni][0] + bv[ni].x;
            v0.y = acc[mi][ni][1] + bv[ni].y;
            v1.x = acc[mi][ni][2] + bv[ni].x;
            v1.y = acc[mi][ni][3] + bv[ni].y;
            if (EPI == 1) {
                v0.x = 1.f / (1.f + expf(-v0.x));
                v0.y = 1.f / (1.f + expf(-v0.y));
                v1.x = 1.f / (1.f + expf(-v1.x));
                v1.y = 1.f / (1.f + expf(-v1.y));
            }
            *(float2*)(C + (size_t)r * GN + ecol0 + ni * 8)       = v0;
            *(float2*)(C + (size_t)(r + 8) * GN + ecol0 + ni * 8) = v1;
            if (WSPLIT) {
                *(uint32_t*)(Ch + (size_t)r * GN + ecol0 + ni * 8)       = hipack(v0.x, v0.y);
                *(uint32_t*)(Cl + (size_t)r * GN + ecol0 + ni * 8)       = lopack(v0.x, v0.y);
                *(uint32_t*)(Ch + (size_t)(r + 8) * GN + ecol0 + ni * 8) = hipack(v1.x, v1.y);
                *(uint32_t*)(Cl + (size_t)(r + 8) * GN + ecol0 + ni * 8) = lopack(v1.x, v1.y);
            }
        }
    }
}

// ---------------------------------------------------------------------------
// Scan: R12 best (R5 body + early release), emitting pre-split states.
// ---------------------------------------------------------------------------
#define SCAN_SMEM (32768 * 2 + 2048)

__global__ __launch_bounds__(256, 1)
void scan_mma(const float* __restrict__ A)
{
    extern __shared__ unsigned char sms[];
    unsigned char* SH = sms;
    unsigned char* SL = sms + 32768;
    float* RED        = (float*)(sms + 65536);

    const int tid = threadIdx.x;
    const int w   = tid >> 5;
    const int l   = tid & 31;
    const int eBase = blockIdx.x * EPER;

    const uint32_t shb = smem_u32(SH);
    const uint32_t slb = smem_u32(SL);

    for (int i = tid * 16; i < 16384; i += 256 * 16) {
        *(uint4*)(SH + 16384 + i) = make_uint4(0, 0, 0, 0);
        *(uint4*)(SL + 16384 + i) = make_uint4(0, 0, 0, 0);
    }

    uint32_t uH[8][2], uL[8][2];
    {
        const int e_row = eBase + (l >> 2);
#pragma unroll
        for (int j = 0; j < 8; j++) {
#pragma unroll
            for (int r = 0; r < 2; r++) {
                int k = 128 * w + 16 * j + 2 * (l & 3) + 8 * r;
                float2 av = *(const float2*)(A + (size_t)e_row * DIMD + k);
                uH[j][r] = hipack(av.x, av.y);
                uL[j][r] = lopack(av.x, av.y);
            }
        }
    }

    const int g    = l >> 3;
    const int lrow = (g & 1) * 8 + (l & 7);
    const int lkh  = (g >> 1) & 1;
    const uint32_t lsw    = (uint32_t)((lrow & 7) << 4);
    const uint32_t cbase  = (uint32_t)(256 * w + 16 * lkh);
    const uint32_t rowoff = (uint32_t)(lrow * 2048);

    const int b_o = tid >> 3;
    const int e_o = tid & 7;

    float u_r = 0.f, g_r = 0.f, i_r = 0.f;
    if (tid < 64) {
        size_t idx0 = (size_t)b_o * SEQ * DIMD + (size_t)(eBase + e_o);
        u_r = g_u[idx0]; g_r = g_gate[idx0]; i_r = g_inp[idx0];
    }

    const uint32_t stsw = (uint32_t)((w & 7) << 4);

    __syncthreads();

    for (int t = 0; t < SEQ; t++) {
        const uint4* srow = (const uint4*)(&g_sp[t & 1][w * DIMD]);
        uint4 p[8];
#pragma unroll
        for (int i = 0; i < 8; i++) p[i] = ldcg4(srow + i * 32 + l);

#pragma unroll
        for (int i = 0; i < 8; i++) {
            uint32_t h0 = __byte_perm(p[i].x, p[i].y, 0x5410);
            uint32_t h1 = __byte_perm(p[i].z, p[i].w, 0x5410);
            uint32_t q0 = __byte_perm(p[i].x, p[i].y, 0x7632);
            uint32_t q1 = __byte_perm(p[i].z, p[i].w, 0x7632);
            uint32_t cb = ((uint32_t)(256 * i + 8 * l)) ^ stsw;
            *(uint2*)(SH + w * 2048 + cb) = make_uint2(h0, h1);
            *(uint2*)(SL + w * 2048 + cb) = make_uint2(q0, q1);
        }
        __syncthreads();

        float acc0[4] = {0.f, 0.f, 0.f, 0.f};
        float acc1[4] = {0.f, 0.f, 0.f, 0.f};
#pragma unroll
        for (int j = 0; j < 8; j++) {
            uint32_t cb = (cbase + 32u * j) ^ lsw;
            uint32_t ah[4], as[4];
            LDSM4(ah, shb + rowoff + cb);
            LDSM4(as, slb + rowoff + cb);
            float* acc = (j & 1) ? acc1 : acc0;
            MMA16816(acc, ah, uH[j]);
            MMA16816(acc, ah, uL[j]);
            MMA16816(acc, as, uH[j]);
        }
        float c0 = acc0[0] + acc1[0];
        float c1 = acc0[1] + acc1[1];

        *(float2*)&RED[w * 64 + (l >> 2) * 8 + 2 * (l & 3)] = make_float2(c0, c1);
        __syncthreads();

        if (tid < 64) {
            float y = 0.f;
#pragma unroll
            for (int ww = 0; ww < 8; ww++) y += RED[ww * 64 + tid];

            float sv = tanhf(y + u_r);
            sv = g_r * sv + (1.f - g_r) * i_r;

            uint32_t fui = __float_as_uint(sv);
            float resid = sv - __uint_as_float(fui & 0xFFFF0000u);
            uint32_t lo2;
            asm("cvt.rn.bf16x2.f32 %0, %1, %2;" : "=r"(lo2) : "f"(0.f), "f"(resid));

            size_t sidx = ((size_t)b_o * SEQ + t) * DIMD + eBase + e_o;
            g_sh[sidx] = (unsigned short)(fui >> 16);
            g_sl[sidx] = (unsigned short)(lo2 & 0xFFFFu);

            uint32_t packed = (fui >> 16) | (lo2 << 16);
            g_sp[(t + 1) & 1][b_o * DIMD + eBase + e_o] = packed;

            if (t + 1 < SEQ) {
                size_t idx = ((size_t)b_o * SEQ + (t + 1)) * DIMD + (eBase + e_o);
                u_r = g_u[idx]; g_r = g_gate[idx]; i_r = g_inp[idx];
            }

            asm volatile("bar.sync 3, 64;" ::: "memory");
            if (tid == 0) {
                red_release_add1(&g_counter);
                const unsigned target = (unsigned)NSCAN * (unsigned)(t + 1);
                while (ld_acquire(&g_counter) < target) { }
            }
        }
        __syncthreads();
    }
}

// ---------------------------------------------------------------------------
// kernel_launch
// ---------------------------------------------------------------------------
extern "C" void kernel_launch(void* const* d_in, const int* in_sizes, int n_in,
                              void* d_out, int out_size)
{
    (void)in_sizes; (void)n_in; (void)out_size;

    const float* x      = (const float*)d_in[0];
    const float* A      = (const float*)d_in[1];
    const float* Bmat   = (const float*)d_in[2];
    const float* W_in   = (const float*)d_in[3];
    const float* b_in   = (const float*)d_in[4];
    const float* W_gate = (const float*)d_in[5];
    const float* b_gate = (const float*)d_in[6];
    const float* W_out  = (const float*)d_in[7];
    const float* b_out  = (const float*)d_in[8];
    float* out          = (float*)d_out;

    void *p_inp, *p_gate, *p_u;
    void *p_xh, *p_xl, *p_ih, *p_il, *p_sh, *p_sl, *p_wh, *p_wl;
    cudaGetSymbolAddress(&p_inp, g_inp);
    cudaGetSymbolAddress(&p_gate, g_gate);
    cudaGetSymbolAddress(&p_u, g_u);
    cudaGetSymbolAddress(&p_xh, g_xh);
    cudaGetSymbolAddress(&p_xl, g_xl);
    cudaGetSymbolAddress(&p_ih, g_ih);
    cudaGetSymbolAddress(&p_il, g_il);
    cudaGetSymbolAddress(&p_sh, g_sh);
    cudaGetSymbolAddress(&p_sl, g_sl);
    cudaGetSymbolAddress(&p_wh, g_wh);
    cudaGetSymbolAddress(&p_wl, g_wl);

    float* inp  = (float*)p_inp;
    float* gate = (float*)p_gate;
    float* u    = (float*)p_u;
    unsigned short* xh = (unsigned short*)p_xh;
    unsigned short* xl = (unsigned short*)p_xl;
    unsigned short* ih = (unsigned short*)p_ih;
    unsigned short* il = (unsigned short*)p_il;
    unsigned short* sh = (unsigned short*)p_sh;
    unsigned short* sl = (unsigned short*)p_sl;
    unsigned short* wh = (unsigned short*)p_wh;
    unsigned short* wl = (unsigned short*)p_wl;

    cudaFuncSetAttribute(scan_mma, cudaFuncAttributeMaxDynamicSharedMemorySize, SCAN_SMEM);
    cudaFuncSetAttribute(gemm_cp<0, 0>, cudaFuncAttributeMaxDynamicSharedMemorySize, GEMM_SMEM);
    cudaFuncSetAttribute(gemm_cp<0, 1>, cudaFuncAttributeMaxDynamicSharedMemorySize, GEMM_SMEM);
    cudaFuncSetAttribute(gemm_cp<1, 0>, cudaFuncAttributeMaxDynamicSharedMemorySize, GEMM_SMEM);

    init_kernel<<<(BATCH * DIMD + 255) / 256, 256>>>();

    // pre-split x and weights
    {
        const int n4x = MTOT * DIMD / 4;
        split_kernel<<<(n4x + 255) / 256, 256>>>((const float4*)x,
            (uint2*)xh, (uint2*)xl, n4x);
        const int n4w = DIMD * DIMD / 4;
        const float* Ws[4] = {W_in, W_gate, Bmat, W_out};
        for (int i = 0; i < 4; i++)
            split_kernel<<<(n4w + 255) / 256, 256>>>((const float4*)Ws[i],
                (uint2*)(wh + (size_t)i * DIMD * DIMD),
                (uint2*)(wl + (size_t)i * DIMD * DIMD), n4w);
    }

    dim3 gg(DIMD / 128, MTOT / 128);   // (8, 256)

    // 1) inp = x @ W_in^T + b_in   (also emit split inp)
    gemm_cp<0, 1><<<gg, 256, GEMM_SMEM>>>(xh, xl,
        wh + 0 * (size_t)DIMD * DIMD, wl + 0 * (size_t)DIMD * DIMD,
        b_in, inp, ih, il);
    // 2) gate = sigmoid(inp @ W_gate^T + b_gate)
    gemm_cp<1, 0><<<gg, 256, GEMM_SMEM>>>(ih, il,
        wh + 1 * (size_t)DIMD * DIMD, wl + 1 * (size_t)DIMD * DIMD,
        b_gate, gate, nullptr, nullptr);
    // 3) u = inp @ B^T
    gemm_cp<0, 0><<<gg, 256, GEMM_SMEM>>>(ih, il,
        wh + 2 * (size_t)DIMD * DIMD, wl + 2 * (size_t)DIMD * DIMD,
        nullptr, u, nullptr, nullptr);
    // 4) scan (emits split states)
    scan_mma<<<NSCAN, 256, SCAN_SMEM>>>(A);
    // 5) out = states @ W_out^T + b_out
    gemm_cp<0, 0><<<gg, 256, GEMM_SMEM>>>(sh, sl,
        wh + 3 * (size_t)DIMD * DIMD, wl + 3 * (size_t)DIMD * DIMD,
        b_out, out, nullptr, nullptr);
}

// round 14
// speedup vs baseline: 1.0382x; 1.0382x over previous
#include <cuda_runtime.h>
#include <math.h>
#include <stdint.h>

// ---------------------------------------------------------------------------
// Problem constants
// ---------------------------------------------------------------------------
#define DIMD  1024
#define BATCH 8
#define SEQ   4096
#define MTOT  (BATCH * SEQ)
#define NSCAN 128
#define EPER  (DIMD / NSCAN)   // 8

// ---------------------------------------------------------------------------
// Scratch (device-global; no allocation allowed)
// ---------------------------------------------------------------------------
__device__ float    g_inp   [(size_t)MTOT * DIMD];
__device__ float    g_gate  [(size_t)MTOT * DIMD];
__device__ float    g_u     [(size_t)MTOT * DIMD];
__device__ float    g_states[(size_t)MTOT * DIMD];
__device__ uint32_t g_sp[2][BATCH * DIMD];   // packed state (bf16 hi | bf16 lo<<16)
__device__ unsigned g_counter;

// ---------------------------------------------------------------------------
// Helpers
// ---------------------------------------------------------------------------
__device__ __forceinline__ uint32_t smem_u32(const void* p) {
    uint32_t a;
    asm("{ .reg .u64 t; cvta.to.shared.u64 t, %1; cvt.u32.u64 %0, t; }" : "=r"(a) : "l"(p));
    return a;
}

#define LDSM4(r, addr)                                                        \
    asm volatile("ldmatrix.sync.aligned.m8n8.x4.shared.b16 {%0,%1,%2,%3}, [%4];" \
        : "=r"((r)[0]), "=r"((r)[1]), "=r"((r)[2]), "=r"((r)[3]) : "r"(addr))

#define MMA16816(d, a, b)                                                     \
    asm volatile("mma.sync.aligned.m16n8k16.row.col.f32.bf16.bf16.f32 "       \
        "{%0,%1,%2,%3}, {%4,%5,%6,%7}, {%8,%9}, {%0,%1,%2,%3};"               \
        : "+f"((d)[0]), "+f"((d)[1]), "+f"((d)[2]), "+f"((d)[3])              \
        : "r"((a)[0]), "r"((a)[1]), "r"((a)[2]), "r"((a)[3]),                 \
          "r"((b)[0]), "r"((b)[1]))

__device__ __forceinline__ uint32_t hipack(float x0, float x1) {
    return __byte_perm(__float_as_uint(x0), __float_as_uint(x1), 0x7632);
}
__device__ __forceinline__ uint32_t lopack(float x0, float x1) {
    float t0 = __uint_as_float(__float_as_uint(x0) & 0xFFFF0000u);
    float t1 = __uint_as_float(__float_as_uint(x1) & 0xFFFF0000u);
    float r0 = x0 - t0, r1 = x1 - t1;
    uint32_t d;
    asm("cvt.rn.bf16x2.f32 %0, %1, %2;" : "=r"(d) : "f"(r1), "f"(r0));
    return d;
}
__device__ __forceinline__ void split8(const float4& a, const float4& b,
                                       uint4& hi, uint4& lo) {
    hi.x = hipack(a.x, a.y); hi.y = hipack(a.z, a.w);
    hi.z = hipack(b.x, b.y); hi.w = hipack(b.z, b.w);
    lo.x = lopack(a.x, a.y); lo.y = lopack(a.z, a.w);
    lo.z = lopack(b.x, b.y); lo.w = lopack(b.z, b.w);
}

__device__ __forceinline__ uint32_t swz(int row, int half) {
    return (uint32_t)(row * 32 + ((half ^ ((row >> 2) & 1)) << 4));
}

__device__ __forceinline__ uint4 ldcg4(const uint4* p) {
    uint4 v;
    asm volatile("ld.global.cg.v4.u32 {%0,%1,%2,%3}, [%4];"
                 : "=r"(v.x), "=r"(v.y), "=r"(v.z), "=r"(v.w) : "l"(p));
    return v;
}
__device__ __forceinline__ void red_release_add1(unsigned* p) {
    asm volatile("red.release.gpu.global.add.u32 [%0], 1;" :: "l"(p) : "memory");
}
__device__ __forceinline__ unsigned ld_acquire(const unsigned* p) {
    unsigned v;
    asm volatile("ld.acquire.gpu.global.u32 %0, [%1];" : "=r"(v) : "l"(p) : "memory");
    return v;
}

// ---------------------------------------------------------------------------
// Init kernel
// ---------------------------------------------------------------------------
__global__ void init_kernel() {
    int t = blockIdx.x * blockDim.x + threadIdx.x;
    if (t < BATCH * DIMD) { g_sp[0][t] = 0u; g_sp[1][t] = 0u; }
    if (t == 0) g_counter = 0u;
}

// ---------------------------------------------------------------------------
// bf16 3x-split tensor-core GEMM (R12 version, measured 597us each)
// ---------------------------------------------------------------------------
#define GK 1024
#define GN 1024
#define NCHUNK (GK / 16)

template <int EPI>
__global__ __launch_bounds__(256, 2)
void gemm_mma(const float* __restrict__ X, const float* __restrict__ W,
              const float* __restrict__ bias, float* __restrict__ C)
{
    __shared__ __align__(1024) unsigned char sm[2][4][4096];

    const int tid = threadIdx.x;
    const int wid = tid >> 5, l = tid & 31;
    const int bm = blockIdx.y * 128, bn = blockIdx.x * 128;
    const int wm = wid & 1, wn = wid >> 1;

    const int srow = tid >> 1, shalf = tid & 1;
    const float* Xp = X + (size_t)(bm + srow) * GK + shalf * 8;
    const float* Wp = W + (size_t)(bn + srow) * GK + shalf * 8;
    const uint32_t soff = swz(srow, shalf);

    const int lrow = l & 15, lhalf = l >> 4;
    uint32_t offA[4], offB[2];
#pragma unroll
    for (int mi = 0; mi < 4; mi++) offA[mi] = swz(wm * 64 + mi * 16 + lrow, lhalf);
#pragma unroll
    for (int gi = 0; gi < 2; gi++) offB[gi] = swz(wn * 32 + gi * 16 + lrow, lhalf);

    const uint32_t smbase = smem_u32(&sm[0][0][0]);

    float acc[4][4][4];
#pragma unroll
    for (int mi = 0; mi < 4; mi++)
#pragma unroll
        for (int ni = 0; ni < 4; ni++)
#pragma unroll
            for (int r = 0; r < 4; r++) acc[mi][ni][r] = 0.f;

    {
        float4 a0 = *(const float4*)(Xp + 0), a1 = *(const float4*)(Xp + 4);
        float4 b0 = *(const float4*)(Wp + 0), b1 = *(const float4*)(Wp + 4);
        uint4 hiA, loA, hiB, loB;
        split8(a0, a1, hiA, loA);
        split8(b0, b1, hiB, loB);
        *(uint4*)(&sm[0][0][soff]) = hiA;
        *(uint4*)(&sm[0][1][soff]) = loA;
        *(uint4*)(&sm[0][2][soff]) = hiB;
        *(uint4*)(&sm[0][3][soff]) = loB;
    }
    __syncthreads();

    for (int c = 0; c < NCHUNK; c++) {
        float4 na0, na1, nb0, nb1;
        if (c + 1 < NCHUNK) {
            const int kc = (c + 1) * 16;
            na0 = *(const float4*)(Xp + kc);     na1 = *(const float4*)(Xp + kc + 4);
            nb0 = *(const float4*)(Wp + kc);     nb1 = *(const float4*)(Wp + kc + 4);
        }

        const uint32_t sb = smbase + (uint32_t)(c & 1) * 16384u;

        uint32_t ah[4][4], al[4][4];
#pragma unroll
        for (int mi = 0; mi < 4; mi++) {
            LDSM4(ah[mi], sb + 0 * 4096u + offA[mi]);
            LDSM4(al[mi], sb + 1 * 4096u + offA[mi]);
        }
        uint32_t bh[4][2], bl[4][2];
#pragma unroll
        for (int gi = 0; gi < 2; gi++) {
            uint32_t t[4];
            LDSM4(t, sb + 2 * 4096u + offB[gi]);
            bh[2 * gi + 0][0] = t[0]; bh[2 * gi + 0][1] = t[2];
            bh[2 * gi + 1][0] = t[1]; bh[2 * gi + 1][1] = t[3];
            LDSM4(t, sb + 3 * 4096u + offB[gi]);
            bl[2 * gi + 0][0] = t[0]; bl[2 * gi + 0][1] = t[2];
            bl[2 * gi + 1][0] = t[1]; bl[2 * gi + 1][1] = t[3];
        }

#pragma unroll
        for (int mi = 0; mi < 4; mi++)
#pragma unroll
            for (int ni = 0; ni < 4; ni++)
                MMA16816(acc[mi][ni], ah[mi], bh[ni]);
#pragma unroll
        for (int mi = 0; mi < 4; mi++)
#pragma unroll
            for (int ni = 0; ni < 4; ni++)
                MMA16816(acc[mi][ni], ah[mi], bl[ni]);
#pragma unroll
        for (int mi = 0; mi < 4; mi++)
#pragma unroll
            for (int ni = 0; ni < 4; ni++)
                MMA16816(acc[mi][ni], al[mi], bh[ni]);

        if (c + 1 < NCHUNK) {
            __syncthreads();
            const int s = (c + 1) & 1;
            uint4 hiA, loA, hiB, loB;
            split8(na0, na1, hiA, loA);
            split8(nb0, nb1, hiB, loB);
            *(uint4*)(&sm[s][0][soff]) = hiA;
            *(uint4*)(&sm[s][1][soff]) = loA;
            *(uint4*)(&sm[s][2][soff]) = hiB;
            *(uint4*)(&sm[s][3][soff]) = loB;
            __syncthreads();
        }
    }

    const int erow  = bm + wm * 64 + (l >> 2);
    const int ecol0 = bn + wn * 32 + 2 * (l & 3);

    float2 bv[4];
#pragma unroll
    for (int ni = 0; ni < 4; ni++) {
        if (bias) {
            bv[ni].x = bias[ecol0 + ni * 8];
            bv[ni].y = bias[ecol0 + ni * 8 + 1];
        } else {
            bv[ni].x = 0.f; bv[ni].y = 0.f;
        }
    }

#pragma unroll
    for (int mi = 0; mi < 4; mi++) {
#pragma unroll
        for (int ni = 0; ni < 4; ni++) {
            const int r = erow + mi * 16;
            float2 v0, v1;
            v0.x = acc[mi][ni][0] + bv[ni].x;
            v0.y = acc[mi][ni][1] + bv[ni].y;
            v1.x = acc[mi][ni][2] + bv[ni].x;
            v1.y = acc[mi][ni][3] + bv[ni].y;
            if (EPI == 1) {
                v0.x = 1.f / (1.f + expf(-v0.x));
                v0.y = 1.f / (1.f + expf(-v0.y));
                v1.x = 1.f / (1.f + expf(-v1.x));
                v1.y = 1.f / (1.f + expf(-v1.y));
            }
            *(float2*)(C + (size_t)r * GN + ecol0 + ni * 8)       = v0;
            *(float2*)(C + (size_t)(r + 8) * GN + ecol0 + ni * 8) = v1;
        }
    }
}

// ---------------------------------------------------------------------------
// Scan: R12 structure with WARP-LOCAL staging.
// Warp w now loads k-seg [128w,128w+128) of ALL 8 batch rows and writes
// exactly the SMEM column window [256w,256w+256) its own ldmatrix reads
// (rows 0-7; rows 8-15 are static zero pad). The post-staging sync becomes
// __syncwarp -> only 2 CTA-wide barriers per step (S2 partials, S3 merged).
// Early release (bar.sync 3,64 -> red.release) kept from R12.
// ---------------------------------------------------------------------------
#define SCAN_SMEM (32768 * 2 + 2048)

__global__ __launch_bounds__(256, 1)
void scan_mma(const float* __restrict__ A)
{
    extern __shared__ unsigned char sms[];
    unsigned char* SH = sms;                    // 16 x 2048 B (rows 8-15 zero pad)
    unsigned char* SL = sms + 32768;
    float* RED        = (float*)(sms + 65536);  // [8][64]

    const int tid = threadIdx.x;
    const int w   = tid >> 5;
    const int l   = tid & 31;
    const int eBase = blockIdx.x * EPER;

    const uint32_t shb = smem_u32(SH);
    const uint32_t slb = smem_u32(SL);

    // zero pad rows 8..15 once
    for (int i = tid * 16; i < 16384; i += 256 * 16) {
        *(uint4*)(SH + 16384 + i) = make_uint4(0, 0, 0, 0);
        *(uint4*)(SL + 16384 + i) = make_uint4(0, 0, 0, 0);
    }

    // --- stationary B fragments: B[k][n] = Amat[eBase+n][k], pre-split hi/lo
    uint32_t uH[8][2], uL[8][2];
    {
        const int e_row = eBase + (l >> 2);
#pragma unroll
        for (int j = 0; j < 8; j++) {
#pragma unroll
            for (int r = 0; r < 2; r++) {
                int k = 128 * w + 16 * j + 2 * (l & 3) + 8 * r;
                float2 av = *(const float2*)(A + (size_t)e_row * DIMD + k);
                uH[j][r] = hipack(av.x, av.y);
                uL[j][r] = lopack(av.x, av.y);
            }
        }
    }

    // --- ldmatrix lane geometry (A-operand, 16x16 tiles)
    const int g    = l >> 3;
    const int lrow = (g & 1) * 8 + (l & 7);
    const int lkh  = (g >> 1) & 1;
    const uint32_t lsw    = (uint32_t)((lrow & 7) << 4);
    const uint32_t cbase  = (uint32_t)(256 * w + 16 * lkh);
    const uint32_t rowoff = (uint32_t)(lrow * 2048);

    // --- epilogue mapping (threads 0..63 own one (b,e) output)
    const int b_o = tid >> 3;
    const int e_o = tid & 7;

    float u_r = 0.f, g_r = 0.f, i_r = 0.f;
    if (tid < 64) {
        size_t idx0 = (size_t)b_o * SEQ * DIMD + (size_t)(eBase + e_o);
        u_r = g_u[idx0]; g_r = g_gate[idx0]; i_r = g_inp[idx0];
    }

    // --- warp-local staging geometry: warp w, lane l covers packed words
    //     kbase + 4l .. kbase + 4l + 3 of EVERY batch row (kbase = 128w)
    const uint32_t kbase   = 128u * (uint32_t)w;
    const uint32_t scolbase = 256u * (uint32_t)w + 8u * (uint32_t)l; // tile byte col

    __syncthreads();   // zero-pad visible

    for (int t = 0; t < SEQ; t++) {
        // 1) load packed state: this warp's k-segment of all 8 batch rows
        const uint32_t* sp = g_sp[t & 1];
        uint4 p[8];
#pragma unroll
        for (int b = 0; b < 8; b++)
            p[b] = ldcg4((const uint4*)(sp + (uint32_t)b * DIMD + kbase + 4u * l));

        // 2) unpack into the SMEM window THIS warp's ldmatrix reads
#pragma unroll
        for (int b = 0; b < 8; b++) {
            uint32_t h0 = __byte_perm(p[b].x, p[b].y, 0x5410);
            uint32_t h1 = __byte_perm(p[b].z, p[b].w, 0x5410);
            uint32_t q0 = __byte_perm(p[b].x, p[b].y, 0x7632);
            uint32_t q1 = __byte_perm(p[b].z, p[b].w, 0x7632);
            uint32_t cb = scolbase ^ ((uint32_t)b << 4);
            *(uint2*)(SH + b * 2048 + cb) = make_uint2(h0, h1);
            *(uint2*)(SL + b * 2048 + cb) = make_uint2(q0, q1);
        }
        __syncwarp();   // warp-local staging complete (no CTA barrier!)

        // 3) 8 chunks x 3 split MMAs
        float acc0[4] = {0.f, 0.f, 0.f, 0.f};
        float acc1[4] = {0.f, 0.f, 0.f, 0.f};
#pragma unroll
        for (int j = 0; j < 8; j++) {
            uint32_t cb = (cbase + 32u * j) ^ lsw;
            uint32_t ah[4], as[4];
            LDSM4(ah, shb + rowoff + cb);
            LDSM4(as, slb + rowoff + cb);
            float* acc = (j & 1) ? acc1 : acc0;
            MMA16816(acc, ah, uH[j]);
            MMA16816(acc, ah, uL[j]);
            MMA16816(acc, as, uH[j]);
        }
        float c0 = acc0[0] + acc1[0];
        float c1 = acc0[1] + acc1[1];

        // 4) cross-warp reduce partials
        *(float2*)&RED[w * 64 + (l >> 2) * 8 + 2 * (l & 3)] = make_float2(c0, c1);
        __syncthreads();   // S2: partials visible

        // 5) epilogue (threads 0-63) -> early release -> single merged sync
        if (tid < 64) {
            float y = 0.f;
#pragma unroll
            for (int ww = 0; ww < 8; ww++) y += RED[ww * 64 + tid];

            float sv = tanhf(y + u_r);
            sv = g_r * sv + (1.f - g_r) * i_r;

            g_states[((size_t)b_o * SEQ + t) * DIMD + eBase + e_o] = sv;

            uint32_t fui = __float_as_uint(sv);
            float resid = sv - __uint_as_float(fui & 0xFFFF0000u);
            uint32_t lo2;
            asm("cvt.rn.bf16x2.f32 %0, %1, %2;" : "=r"(lo2) : "f"(0.f), "f"(resid));
            uint32_t packed = (fui >> 16) | (lo2 << 16);
            g_sp[(t + 1) & 1][b_o * DIMD + eBase + e_o] = packed;

            if (t + 1 < SEQ) {
                size_t idx = ((size_t)b_o * SEQ + (t + 1)) * DIMD + (eBase + e_o);
                u_r = g_u[idx]; g_r = g_gate[idx]; i_r = g_inp[idx];
            }

            // order the 64 epilogue threads' state stores, then release NOW
            asm volatile("bar.sync 3, 64;" ::: "memory");
            if (tid == 0) {
                red_release_add1(&g_counter);
                const unsigned target = (unsigned)NSCAN * (unsigned)(t + 1);
                while (ld_acquire(&g_counter) < target) { }
            }
        }
        __syncthreads();   // S3 (merged): poll done -> state(t+1) readable
    }
}

// ---------------------------------------------------------------------------
// kernel_launch
// ---------------------------------------------------------------------------
extern "C" void kernel_launch(void* const* d_in, const int* in_sizes, int n_in,
                              void* d_out, int out_size)
{
    (void)in_sizes; (void)n_in; (void)out_size;

    const float* x      = (const float*)d_in[0];
    const float* A      = (const float*)d_in[1];
    const float* Bmat   = (const float*)d_in[2];
    const float* W_in   = (const float*)d_in[3];
    const float* b_in   = (const float*)d_in[4];
    const float* W_gate = (const float*)d_in[5];
    const float* b_gate = (const float*)d_in[6];
    const float* W_out  = (const float*)d_in[7];
    const float* b_out  = (const float*)d_in[8];
    float* out          = (float*)d_out;

    void *p_inp, *p_gate, *p_u, *p_states;
    cudaGetSymbolAddress(&p_inp,    g_inp);
    cudaGetSymbolAddress(&p_gate,   g_gate);
    cudaGetSymbolAddress(&p_u,      g_u);
    cudaGetSymbolAddress(&p_states, g_states);

    float* inp    = (float*)p_inp;
    float* gate   = (float*)p_gate;
    float* u      = (float*)p_u;
    float* states = (float*)p_states;

    cudaFuncSetAttribute(scan_mma, cudaFuncAttributeMaxDynamicSharedMemorySize, SCAN_SMEM);

    init_kernel<<<(BATCH * DIMD + 255) / 256, 256>>>();

    dim3 gg(DIMD / 128, MTOT / 128);   // (8, 256)

    gemm_mma<0><<<gg, 256>>>(x, W_in, b_in, inp);
    gemm_mma<1><<<gg, 256>>>(inp, W_gate, b_gate, gate);
    gemm_mma<0><<<gg, 256>>>(inp, Bmat, nullptr, u);
    scan_mma<<<NSCAN, 256, SCAN_SMEM>>>(A);
    gemm_mma<0><<<gg, 256>>>(states, W_out, b_out, out);
}

// round 15
// speedup vs baseline: 1.0519x; 1.0132x over previous
#include <cuda_runtime.h>
#include <math.h>
#include <stdint.h>

// ---------------------------------------------------------------------------
// Problem constants
// ---------------------------------------------------------------------------
#define DIMD  1024
#define BATCH 8
#define SEQ   4096
#define MTOT  (BATCH * SEQ)
#define NSCAN 128
#define EPER  (DIMD / NSCAN)   // 8

// ---------------------------------------------------------------------------
// Scratch (device-global; no allocation allowed)
// ---------------------------------------------------------------------------
__device__ float    g_inp   [(size_t)MTOT * DIMD];
__device__ float    g_gate  [(size_t)MTOT * DIMD];
__device__ float    g_u     [(size_t)MTOT * DIMD];
__device__ float    g_states[(size_t)MTOT * DIMD];
__device__ uint32_t g_sp[2][BATCH * DIMD];   // packed state (bf16 hi | bf16 lo<<16)
__device__ unsigned g_counter;

// ---------------------------------------------------------------------------
// Helpers
// ---------------------------------------------------------------------------
__device__ __forceinline__ uint32_t smem_u32(const void* p) {
    uint32_t a;
    asm("{ .reg .u64 t; cvta.to.shared.u64 t, %1; cvt.u32.u64 %0, t; }" : "=r"(a) : "l"(p));
    return a;
}

#define LDSM4(r, addr)                                                        \
    asm volatile("ldmatrix.sync.aligned.m8n8.x4.shared.b16 {%0,%1,%2,%3}, [%4];" \
        : "=r"((r)[0]), "=r"((r)[1]), "=r"((r)[2]), "=r"((r)[3]) : "r"(addr))

#define LDSM2(r0, r1, addr)                                                   \
    asm volatile("ldmatrix.sync.aligned.m8n8.x2.shared.b16 {%0,%1}, [%2];"    \
        : "=r"(r0), "=r"(r1) : "r"(addr))

#define MMA16816(d, a, b)                                                     \
    asm volatile("mma.sync.aligned.m16n8k16.row.col.f32.bf16.bf16.f32 "       \
        "{%0,%1,%2,%3}, {%4,%5,%6,%7}, {%8,%9}, {%0,%1,%2,%3};"               \
        : "+f"((d)[0]), "+f"((d)[1]), "+f"((d)[2]), "+f"((d)[3])              \
        : "r"((a)[0]), "r"((a)[1]), "r"((a)[2]), "r"((a)[3]),                 \
          "r"((b)[0]), "r"((b)[1]))

// A rows 8-15 structurally zero -> a1 = a3 = 0 (validated R7/R8)
#define MMAZ(d, a0v, a2v, b)                                                  \
    asm volatile("mma.sync.aligned.m16n8k16.row.col.f32.bf16.bf16.f32 "       \
        "{%0,%1,%2,%3}, {%4,%5,%6,%7}, {%8,%9}, {%0,%1,%2,%3};"               \
        : "+f"((d)[0]), "+f"((d)[1]), "+f"((d)[2]), "+f"((d)[3])              \
        : "r"(a0v), "r"(0u), "r"(a2v), "r"(0u),                               \
          "r"((b)[0]), "r"((b)[1]))

__device__ __forceinline__ uint32_t hipack(float x0, float x1) {
    return __byte_perm(__float_as_uint(x0), __float_as_uint(x1), 0x7632);
}
__device__ __forceinline__ uint32_t lopack(float x0, float x1) {
    float t0 = __uint_as_float(__float_as_uint(x0) & 0xFFFF0000u);
    float t1 = __uint_as_float(__float_as_uint(x1) & 0xFFFF0000u);
    float r0 = x0 - t0, r1 = x1 - t1;
    uint32_t d;
    asm("cvt.rn.bf16x2.f32 %0, %1, %2;" : "=r"(d) : "f"(r1), "f"(r0));
    return d;
}
__device__ __forceinline__ void split8(const float4& a, const float4& b,
                                       uint4& hi, uint4& lo) {
    hi.x = hipack(a.x, a.y); hi.y = hipack(a.z, a.w);
    hi.z = hipack(b.x, b.y); hi.w = hipack(b.z, b.w);
    lo.x = lopack(a.x, a.y); lo.y = lopack(a.z, a.w);
    lo.z = lopack(b.x, b.y); lo.w = lopack(b.z, b.w);
}

__device__ __forceinline__ uint32_t swz(int row, int half) {
    return (uint32_t)(row * 32 + ((half ^ ((row >> 2) & 1)) << 4));
}

__device__ __forceinline__ uint4 ldcg4(const uint4* p) {
    uint4 v;
    asm volatile("ld.global.cg.v4.u32 {%0,%1,%2,%3}, [%4];"
                 : "=r"(v.x), "=r"(v.y), "=r"(v.z), "=r"(v.w) : "l"(p));
    return v;
}
__device__ __forceinline__ void red_release_add1(unsigned* p) {
    asm volatile("red.release.gpu.global.add.u32 [%0], 1;" :: "l"(p) : "memory");
}
__device__ __forceinline__ unsigned ld_acquire(const unsigned* p) {
    unsigned v;
    asm volatile("ld.acquire.gpu.global.u32 %0, [%1];" : "=r"(v) : "l"(p) : "memory");
    return v;
}

// ---------------------------------------------------------------------------
// Init kernel
// ---------------------------------------------------------------------------
__global__ void init_kernel() {
    int t = blockIdx.x * blockDim.x + threadIdx.x;
    if (t < BATCH * DIMD) { g_sp[0][t] = 0u; g_sp[1][t] = 0u; }
    if (t == 0) g_counter = 0u;
}

// ---------------------------------------------------------------------------
// bf16 3x-split tensor-core GEMM (R12/R14 version, measured 597us each)
// ---------------------------------------------------------------------------
#define GK 1024
#define GN 1024
#define NCHUNK (GK / 16)

template <int EPI>
__global__ __launch_bounds__(256, 2)
void gemm_mma(const float* __restrict__ X, const float* __restrict__ W,
              const float* __restrict__ bias, float* __restrict__ C)
{
    __shared__ __align__(1024) unsigned char sm[2][4][4096];

    const int tid = threadIdx.x;
    const int wid = tid >> 5, l = tid & 31;
    const int bm = blockIdx.y * 128, bn = blockIdx.x * 128;
    const int wm = wid & 1, wn = wid >> 1;

    const int srow = tid >> 1, shalf = tid & 1;
    const float* Xp = X + (size_t)(bm + srow) * GK + shalf * 8;
    const float* Wp = W + (size_t)(bn + srow) * GK + shalf * 8;
    const uint32_t soff = swz(srow, shalf);

    const int lrow = l & 15, lhalf = l >> 4;
    uint32_t offA[4], offB[2];
#pragma unroll
    for (int mi = 0; mi < 4; mi++) offA[mi] = swz(wm * 64 + mi * 16 + lrow, lhalf);
#pragma unroll
    for (int gi = 0; gi < 2; gi++) offB[gi] = swz(wn * 32 + gi * 16 + lrow, lhalf);

    const uint32_t smbase = smem_u32(&sm[0][0][0]);

    float acc[4][4][4];
#pragma unroll
    for (int mi = 0; mi < 4; mi++)
#pragma unroll
        for (int ni = 0; ni < 4; ni++)
#pragma unroll
            for (int r = 0; r < 4; r++) acc[mi][ni][r] = 0.f;

    {
        float4 a0 = *(const float4*)(Xp + 0), a1 = *(const float4*)(Xp + 4);
        float4 b0 = *(const float4*)(Wp + 0), b1 = *(const float4*)(Wp + 4);
        uint4 hiA, loA, hiB, loB;
        split8(a0, a1, hiA, loA);
        split8(b0, b1, hiB, loB);
        *(uint4*)(&sm[0][0][soff]) = hiA;
        *(uint4*)(&sm[0][1][soff]) = loA;
        *(uint4*)(&sm[0][2][soff]) = hiB;
        *(uint4*)(&sm[0][3][soff]) = loB;
    }
    __syncthreads();

    for (int c = 0; c < NCHUNK; c++) {
        float4 na0, na1, nb0, nb1;
        if (c + 1 < NCHUNK) {
            const int kc = (c + 1) * 16;
            na0 = *(const float4*)(Xp + kc);     na1 = *(const float4*)(Xp + kc + 4);
            nb0 = *(const float4*)(Wp + kc);     nb1 = *(const float4*)(Wp + kc + 4);
        }

        const uint32_t sb = smbase + (uint32_t)(c & 1) * 16384u;

        uint32_t ah[4][4], al[4][4];
#pragma unroll
        for (int mi = 0; mi < 4; mi++) {
            LDSM4(ah[mi], sb + 0 * 4096u + offA[mi]);
            LDSM4(al[mi], sb + 1 * 4096u + offA[mi]);
        }
        uint32_t bh[4][2], bl[4][2];
#pragma unroll
        for (int gi = 0; gi < 2; gi++) {
            uint32_t t[4];
            LDSM4(t, sb + 2 * 4096u + offB[gi]);
            bh[2 * gi + 0][0] = t[0]; bh[2 * gi + 0][1] = t[2];
            bh[2 * gi + 1][0] = t[1]; bh[2 * gi + 1][1] = t[3];
            LDSM4(t, sb + 3 * 4096u + offB[gi]);
            bl[2 * gi + 0][0] = t[0]; bl[2 * gi + 0][1] = t[2];
            bl[2 * gi + 1][0] = t[1]; bl[2 * gi + 1][1] = t[3];
        }

#pragma unroll
        for (int mi = 0; mi < 4; mi++)
#pragma unroll
            for (int ni = 0; ni < 4; ni++)
                MMA16816(acc[mi][ni], ah[mi], bh[ni]);
#pragma unroll
        for (int mi = 0; mi < 4; mi++)
#pragma unroll
            for (int ni = 0; ni < 4; ni++)
                MMA16816(acc[mi][ni], ah[mi], bl[ni]);
#pragma unroll
        for (int mi = 0; mi < 4; mi++)
#pragma unroll
            for (int ni = 0; ni < 4; ni++)
                MMA16816(acc[mi][ni], al[mi], bh[ni]);

        if (c + 1 < NCHUNK) {
            __syncthreads();
            const int s = (c + 1) & 1;
            uint4 hiA, loA, hiB, loB;
            split8(na0, na1, hiA, loA);
            split8(nb0, nb1, hiB, loB);
            *(uint4*)(&sm[s][0][soff]) = hiA;
            *(uint4*)(&sm[s][1][soff]) = loA;
            *(uint4*)(&sm[s][2][soff]) = hiB;
            *(uint4*)(&sm[s][3][soff]) = loB;
            __syncthreads();
        }
    }

    const int erow  = bm + wm * 64 + (l >> 2);
    const int ecol0 = bn + wn * 32 + 2 * (l & 3);

    float2 bv[4];
#pragma unroll
    for (int ni = 0; ni < 4; ni++) {
        if (bias) {
            bv[ni].x = bias[ecol0 + ni * 8];
            bv[ni].y = bias[ecol0 + ni * 8 + 1];
        } else {
            bv[ni].x = 0.f; bv[ni].y = 0.f;
        }
    }

#pragma unroll
    for (int mi = 0; mi < 4; mi++) {
#pragma unroll
        for (int ni = 0; ni < 4; ni++) {
            const int r = erow + mi * 16;
            float2 v0, v1;
            v0.x = acc[mi][ni][0] + bv[ni].x;
            v0.y = acc[mi][ni][1] + bv[ni].y;
            v1.x = acc[mi][ni][2] + bv[ni].x;
            v1.y = acc[mi][ni][3] + bv[ni].y;
            if (EPI == 1) {
                v0.x = 1.f / (1.f + expf(-v0.x));
                v0.y = 1.f / (1.f + expf(-v0.y));
                v1.x = 1.f / (1.f + expf(-v1.x));
                v1.y = 1.f / (1.f + expf(-v1.y));
            }
            *(float2*)(C + (size_t)r * GN + ecol0 + ni * 8)       = v0;
            *(float2*)(C + (size_t)(r + 8) * GN + ecol0 + ni * 8) = v1;
        }
    }
}

// ---------------------------------------------------------------------------
// Scan: R14 structure (warp-local staging, early release, 2 CTA barriers)
// with 8-ROW TILES: ldmatrix.x2 + MMAZ (a1=a3=0). Half the LDSM traffic,
// no zero-pad SMEM (66KB -> 34KB). Same arithmetic => identical results.
// ---------------------------------------------------------------------------
#define SCAN_SMEM (2 * 16384 + 2048)   // SH 8x2048, SL 8x2048, RED [8][64]

__global__ __launch_bounds__(256, 1)
void scan_mma(const float* __restrict__ A)
{
    extern __shared__ unsigned char sms[];
    unsigned char* SH = sms;                    // 8 rows (batch) x 2048 B
    unsigned char* SL = sms + 16384;
    float* RED        = (float*)(sms + 32768);  // [8][64]

    const int tid = threadIdx.x;
    const int w   = tid >> 5;
    const int l   = tid & 31;
    const int eBase = blockIdx.x * EPER;

    const uint32_t shb = smem_u32(SH);
    const uint32_t slb = smem_u32(SL);

    // --- stationary B fragments: B[k][n] = Amat[eBase+n][k], pre-split hi/lo
    uint32_t uH[8][2], uL[8][2];
    {
        const int e_row = eBase + (l >> 2);
#pragma unroll
        for (int j = 0; j < 8; j++) {
#pragma unroll
            for (int r = 0; r < 2; r++) {
                int k = 128 * w + 16 * j + 2 * (l & 3) + 8 * r;
                float2 av = *(const float2*)(A + (size_t)e_row * DIMD + k);
                uH[j][r] = hipack(av.x, av.y);
                uL[j][r] = lopack(av.x, av.y);
            }
        }
    }

    // --- ldmatrix.x2 lane geometry: lanes 0-7 -> matrix0 (k-half 0),
    //     lanes 8-15 -> matrix1 (k-half 1); row = batch = l&7
    const int lr  = l & 7;
    const int sel = (l >> 3) & 1;
    const uint32_t lrow_off = (uint32_t)(lr * 2048);
    const uint32_t lxr      = (uint32_t)(lr << 4);
    const uint32_t cbase    = (uint32_t)(256 * w);

    // --- epilogue mapping (threads 0..63 own one (b,e) output)
    const int b_o = tid >> 3;
    const int e_o = tid & 7;

    float u_r = 0.f, g_r = 0.f, i_r = 0.f;
    if (tid < 64) {
        size_t idx0 = (size_t)b_o * SEQ * DIMD + (size_t)(eBase + e_o);
        u_r = g_u[idx0]; g_r = g_gate[idx0]; i_r = g_inp[idx0];
    }

    // --- warp-local staging geometry: warp w covers packed words
    //     kbase + 4l .. kbase + 4l + 3 of EVERY batch row (kbase = 128w)
    const uint32_t kbase    = 128u * (uint32_t)w;
    const uint32_t scolbase = 256u * (uint32_t)w + 8u * (uint32_t)l;

    __syncthreads();

    for (int t = 0; t < SEQ; t++) {
        // 1) load packed state: this warp's k-segment of all 8 batch rows
        const uint32_t* sp = g_sp[t & 1];
        uint4 p[8];
#pragma unroll
        for (int b = 0; b < 8; b++)
            p[b] = ldcg4((const uint4*)(sp + (uint32_t)b * DIMD + kbase + 4u * l));

        // 2) unpack into the SMEM window THIS warp's ldmatrix reads
#pragma unroll
        for (int b = 0; b < 8; b++) {
            uint32_t h0 = __byte_perm(p[b].x, p[b].y, 0x5410);
            uint32_t h1 = __byte_perm(p[b].z, p[b].w, 0x5410);
            uint32_t q0 = __byte_perm(p[b].x, p[b].y, 0x7632);
            uint32_t q1 = __byte_perm(p[b].z, p[b].w, 0x7632);
            uint32_t cb = scolbase ^ ((uint32_t)b << 4);
            *(uint2*)(SH + b * 2048 + cb) = make_uint2(h0, h1);
            *(uint2*)(SL + b * 2048 + cb) = make_uint2(q0, q1);
        }
        __syncwarp();   // warp-local staging complete (no CTA barrier)

        // 3) 8 chunks x 3 split MMAs, 8-row fragments (LDSM2 + MMAZ)
        float acc0[4] = {0.f, 0.f, 0.f, 0.f};
        float acc1[4] = {0.f, 0.f, 0.f, 0.f};
#pragma unroll
        for (int j = 0; j < 8; j++) {
            uint32_t cb = lrow_off + (((cbase + 32u * j + 16u * sel)) ^ lxr);
            uint32_t h0, h1, s0, s1;
            LDSM2(h0, h1, shb + cb);
            LDSM2(s0, s1, slb + cb);
            float* acc = (j & 1) ? acc1 : acc0;
            MMAZ(acc, h0, h1, uH[j]);
            MMAZ(acc, h0, h1, uL[j]);
            MMAZ(acc, s0, s1, uH[j]);
        }
        float c0 = acc0[0] + acc1[0];
        float c1 = acc0[1] + acc1[1];

        // 4) cross-warp reduce partials (rows l>>2 in 0..7 valid)
        *(float2*)&RED[w * 64 + (l >> 2) * 8 + 2 * (l & 3)] = make_float2(c0, c1);
        __syncthreads();   // S2: partials visible

        // 5) epilogue (threads 0-63) -> early release -> single merged sync
        if (tid < 64) {
            float y = 0.f;
#pragma unroll
            for (int ww = 0; ww < 8; ww++) y += RED[ww * 64 + tid];

            float sv = tanhf(y + u_r);
            sv = g_r * sv + (1.f - g_r) * i_r;

            g_states[((size_t)b_o * SEQ + t) * DIMD + eBase + e_o] = sv;

            uint32_t fui = __float_as_uint(sv);
            float resid = sv - __uint_as_float(fui & 0xFFFF0000u);
            uint32_t lo2;
            asm("cvt.rn.bf16x2.f32 %0, %1, %2;" : "=r"(lo2) : "f"(0.f), "f"(resid));
            uint32_t packed = (fui >> 16) | (lo2 << 16);
            g_sp[(t + 1) & 1][b_o * DIMD + eBase + e_o] = packed;

            if (t + 1 < SEQ) {
                size_t idx = ((size_t)b_o * SEQ + (t + 1)) * DIMD + (eBase + e_o);
                u_r = g_u[idx]; g_r = g_gate[idx]; i_r = g_inp[idx];
            }

            asm volatile("bar.sync 3, 64;" ::: "memory");
            if (tid == 0) {
                red_release_add1(&g_counter);
                const unsigned target = (unsigned)NSCAN * (unsigned)(t + 1);
                while (ld_acquire(&g_counter) < target) { }
            }
        }
        __syncthreads();   // S3 (merged): poll done -> state(t+1) readable
    }
}

// ---------------------------------------------------------------------------
// kernel_launch
// ---------------------------------------------------------------------------
extern "C" void kernel_launch(void* const* d_in, const int* in_sizes, int n_in,
                              void* d_out, int out_size)
{
    (void)in_sizes; (void)n_in; (void)out_size;

    const float* x      = (const float*)d_in[0];
    const float* A      = (const float*)d_in[1];
    const float* Bmat   = (const float*)d_in[2];
    const float* W_in   = (const float*)d_in[3];
    const float* b_in   = (const float*)d_in[4];
    const float* W_gate = (const float*)d_in[5];
    const float* b_gate = (const float*)d_in[6];
    const float* W_out  = (const float*)d_in[7];
    const float* b_out  = (const float*)d_in[8];
    float* out          = (float*)d_out;

    void *p_inp, *p_gate, *p_u, *p_states;
    cudaGetSymbolAddress(&p_inp,    g_inp);
    cudaGetSymbolAddress(&p_gate,   g_gate);
    cudaGetSymbolAddress(&p_u,      g_u);
    cudaGetSymbolAddress(&p_states, g_states);

    float* inp    = (float*)p_inp;
    float* gate   = (float*)p_gate;
    float* u      = (float*)p_u;
    float* states = (float*)p_states;

    cudaFuncSetAttribute(scan_mma, cudaFuncAttributeMaxDynamicSharedMemorySize, SCAN_SMEM);

    init_kernel<<<(BATCH * DIMD + 255) / 256, 256>>>();

    dim3 gg(DIMD / 128, MTOT / 128);   // (8, 256)

    gemm_mma<0><<<gg, 256>>>(x, W_in, b_in, inp);
    gemm_mma<1><<<gg, 256>>>(inp, W_gate, b_gate, gate);
    gemm_mma<0><<<gg, 256>>>(inp, Bmat, nullptr, u);
    scan_mma<<<NSCAN, 256, SCAN_SMEM>>>(A);
    gemm_mma<0><<<gg, 256>>>(states, W_out, b_out, out);
}